// round 14
// baseline (speedup 1.0000x reference)
#include <cuda_runtime.h>
#include <cstdint>

#define DV 16
#define HV 64
#define WV 64
#define NVOX (DV*HV*WV)   /* 65536 voxels */
#define NMAX 250000
#define JJ   55

// Scratch (no allocations allowed)
__device__ __align__(16) float4 g_mv[NVOX * 20];   // 20MB: per-voxel [A,C0..C3] rows
__device__ __align__(16) float4 g_pm[NMAX * 20];   // 80MB: per-point rows (masked only)
__device__ int g_midx[NMAX];                       // compacted masked indices
__device__ int g_uidx[NMAX];                       // compacted unmasked indices
__device__ int g_cnt;                              // masked count
__device__ int g_ucnt;                             // unmasked count
__device__ int g_mask_is_u8;

// ---------------------------------------------------------------------------
// helpers
// ---------------------------------------------------------------------------
static __device__ __forceinline__ unsigned long long ffma2(
    unsigned long long a, unsigned long long b, unsigned long long c) {
    unsigned long long d;
    asm("fma.rn.f32x2 %0, %1, %2, %3;" : "=l"(d) : "l"(a), "l"(b), "l"(c));
    return d;
}
static __device__ __forceinline__ unsigned long long splat2(float w) {
    unsigned long long d;
    asm("mov.b64 %0, {%1, %1};" : "=l"(d) : "f"(w));
    return d;
}
static __device__ __forceinline__ float4 pack2(unsigned long long a, unsigned long long b) {
    float4 r;
    asm("mov.b64 {%0, %1}, %2;" : "=f"(r.x), "=f"(r.y) : "l"(a));
    asm("mov.b64 {%0, %1}, %2;" : "=f"(r.z), "=f"(r.w) : "l"(b));
    return r;
}

// ---------------------------------------------------------------------------
// mask dtype detection + reset
// ---------------------------------------------------------------------------
__global__ void reset_flag_kernel() { g_mask_is_u8 = 0; g_cnt = 0; g_ucnt = 0; }

__global__ void detect_mask_kernel(const unsigned char* __restrict__ m, int N) {
    int i = blockIdx.x * 256 + threadIdx.x;
    int limit = N < 65536 ? N : 65536;
    if (i < limit && (i & 3) != 0 && m[i] != 0)
        atomicOr(&g_mask_is_u8, 1);
}

static __device__ __forceinline__ bool read_mask(const void* mask_raw, int n) {
    if (g_mask_is_u8) return ((const unsigned char*)mask_raw)[n] != 0;
    return ((const int*)mask_raw)[n] != 0;
}

// ---------------------------------------------------------------------------
// compact masked AND unmasked indices (order nondeterministic; outputs keyed
// by the original point index, so final results are deterministic)
// ---------------------------------------------------------------------------
__global__ void compact_mask_kernel(const void* __restrict__ mask_raw, int N) {
    int i = blockIdx.x * 256 + threadIdx.x;
    if (i < N) {
        if (read_mask(mask_raw, i)) g_midx[atomicAdd(&g_cnt, 1)] = i;
        else                        g_uidx[atomicAdd(&g_ucnt, 1)] = i;
    }
}

// ---------------------------------------------------------------------------
// P1: per-voxel pre-blend, TWO voxels per thread.
// blockIdx.y = m (0 = tfs_inv, 1..4 = tfs batch m-1).  M[v] = sum_j vol[j][v]*T_j
// ---------------------------------------------------------------------------
__global__ void __launch_bounds__(256) preblend_vox_kernel(
    const float* __restrict__ vol, const float* __restrict__ tfs,
    const float* __restrict__ tfs_inv)
{
    const int m = blockIdx.y;
    const int v = (blockIdx.x * 256 + threadIdx.x) * 2;
    __shared__ float4 s_T[JJ * 4];
    {
        const float* src = (m == 0) ? tfs_inv : tfs + (m - 1) * JJ * 16;
        float* st = (float*)s_T;
        for (int e = threadIdx.x; e < JJ * 16; e += 256) st[e] = src[e];
    }
    __syncthreads();

    unsigned long long A0=0,A1=0,A2=0,A3=0,A4=0,A5=0,A6=0,A7=0;
    unsigned long long B0=0,B1=0,B2=0,B3=0,B4=0,B5=0,B6=0,B7=0;
    #pragma unroll 11
    for (int j = 0; j < JJ; ++j) {
        float2 w2 = *(const float2*)&vol[j * NVOX + v];
        unsigned long long sa = splat2(w2.x);
        unsigned long long sb = splat2(w2.y);
        const ulonglong2* rp = (const ulonglong2*)&s_T[j * 4];
        ulonglong2 r0 = rp[0], r1 = rp[1], r2 = rp[2], r3 = rp[3];
        A0 = ffma2(sa, r0.x, A0); A1 = ffma2(sa, r0.y, A1);
        A2 = ffma2(sa, r1.x, A2); A3 = ffma2(sa, r1.y, A3);
        A4 = ffma2(sa, r2.x, A4); A5 = ffma2(sa, r2.y, A5);
        A6 = ffma2(sa, r3.x, A6); A7 = ffma2(sa, r3.y, A7);
        B0 = ffma2(sb, r0.x, B0); B1 = ffma2(sb, r0.y, B1);
        B2 = ffma2(sb, r1.x, B2); B3 = ffma2(sb, r1.y, B3);
        B4 = ffma2(sb, r2.x, B4); B5 = ffma2(sb, r2.y, B5);
        B6 = ffma2(sb, r3.x, B6); B7 = ffma2(sb, r3.y, B7);
    }
    float4* out = &g_mv[v * 20 + m * 4];
    out[0] = pack2(A0, A1); out[1] = pack2(A2, A3);
    out[2] = pack2(A4, A5); out[3] = pack2(A6, A7);
    out = &g_mv[(v + 1) * 20 + m * 4];
    out[0] = pack2(B0, B1); out[1] = pack2(B2, B3);
    out[2] = pack2(B4, B5); out[3] = pack2(B6, B7);
}

// ---------------------------------------------------------------------------
// P2: per-point pre-blend over the COMPACTED masked list.
// block = (32, 5): thread (p, m) handles compacted slots i0+p and i0+p+32.
// ---------------------------------------------------------------------------
__global__ void __launch_bounds__(160) preblend_pts_kernel(
    const float* __restrict__ lbsw, const float* __restrict__ tfs,
    const float* __restrict__ tfs_inv)
{
    const int cnt = g_cnt;
    const int i0 = blockIdx.x * 64;
    if (i0 >= cnt) return;

    __shared__ float4 s_T[5][JJ * 4];
    __shared__ float  s_w[JJ][66];
    __shared__ int    s_idx[64];
    const int tid = threadIdx.y * 32 + threadIdx.x;
    {
        float* st = (float*)s_T;
        for (int e = tid; e < 5 * JJ * 16; e += 160) {
            int m = e / (JJ * 16), q = e - m * (JJ * 16);
            st[e] = (m == 0) ? tfs_inv[q] : tfs[(m - 1) * JJ * 16 + q];
        }
        if (tid < 64) s_idx[tid] = (i0 + tid < cnt) ? g_midx[i0 + tid] : -1;
    }
    __syncthreads();
    {
        int cnt2 = min(64, cnt - i0);
        for (int e = tid; e < cnt2 * JJ; e += 160) {
            int p = e / JJ, j = e - p * JJ;
            s_w[j][p] = lbsw[(long)s_idx[p] * JJ + j];
        }
    }
    __syncthreads();

    const int p = threadIdx.x, m = threadIdx.y;
    const int nA = s_idx[p], nB = s_idx[p + 32];

    unsigned long long A0=0,A1=0,A2=0,A3=0,A4=0,A5=0,A6=0,A7=0;
    unsigned long long B0=0,B1=0,B2=0,B3=0,B4=0,B5=0,B6=0,B7=0;
    #pragma unroll 5
    for (int j = 0; j < JJ; ++j) {
        const ulonglong2* rp = (const ulonglong2*)&s_T[m][j * 4];
        ulonglong2 r0 = rp[0], r1 = rp[1], r2 = rp[2], r3 = rp[3];
        unsigned long long sa = splat2(s_w[j][p]);
        unsigned long long sb = splat2(s_w[j][p + 32]);
        A0 = ffma2(sa, r0.x, A0); A1 = ffma2(sa, r0.y, A1);
        A2 = ffma2(sa, r1.x, A2); A3 = ffma2(sa, r1.y, A3);
        A4 = ffma2(sa, r2.x, A4); A5 = ffma2(sa, r2.y, A5);
        A6 = ffma2(sa, r3.x, A6); A7 = ffma2(sa, r3.y, A7);
        B0 = ffma2(sb, r0.x, B0); B1 = ffma2(sb, r0.y, B1);
        B2 = ffma2(sb, r1.x, B2); B3 = ffma2(sb, r1.y, B3);
        B4 = ffma2(sb, r2.x, B4); B5 = ffma2(sb, r2.y, B5);
        B6 = ffma2(sb, r3.x, B6); B7 = ffma2(sb, r3.y, B7);
    }
    if (nA >= 0) {
        float4* out = &g_pm[(long)nA * 20 + m * 4];
        out[0] = pack2(A0, A1); out[1] = pack2(A2, A3);
        out[2] = pack2(A4, A5); out[3] = pack2(A6, A7);
    }
    if (nB >= 0) {
        float4* out = &g_pm[(long)nB * 20 + m * 4];
        out[0] = pack2(B0, B1); out[1] = pack2(B2, B3);
        out[2] = pack2(B4, B5); out[3] = pack2(B6, B7);
    }
}

// ---------------------------------------------------------------------------
// Shared epilogue: 8-lane group holds A rows (k<4, in acc) and C_b rows (k>=4).
// ---------------------------------------------------------------------------
static __device__ __forceinline__ void epilogue(
    float4 acc, int k, int nc, long idx, bool valid,
    float px, float py, float pz,
    const float* __restrict__ shape_off, const float* __restrict__ pose_off,
    const float* __restrict__ poseoff_ori,
    float* __restrict__ out_xd, float* __restrict__ out_w)
{
    const unsigned F = 0xffffffffu;
    const int lane = threadIdx.x & 31;
    const int gbl  = lane & ~7;

    float aval = acc.x * px + acc.y * py + acc.z * pz + acc.w;
    if (k < 3)
        aval += -poseoff_ori[(long)nc * 3 + k]
              + shape_off[idx * 3 + k] + pose_off[idx * 3 + k];

    float sx = __shfl_sync(F, aval, gbl + 0);
    float sy = __shfl_sync(F, aval, gbl + 1);
    float sz = __shfl_sync(F, aval, gbl + 2);

    float4 A0, A1, A2, A3;
    A0.x = __shfl_sync(F, acc.x, gbl + 0); A0.y = __shfl_sync(F, acc.y, gbl + 0);
    A0.z = __shfl_sync(F, acc.z, gbl + 0); A0.w = __shfl_sync(F, acc.w, gbl + 0);
    A1.x = __shfl_sync(F, acc.x, gbl + 1); A1.y = __shfl_sync(F, acc.y, gbl + 1);
    A1.z = __shfl_sync(F, acc.z, gbl + 1); A1.w = __shfl_sync(F, acc.w, gbl + 1);
    A2.x = __shfl_sync(F, acc.x, gbl + 2); A2.y = __shfl_sync(F, acc.y, gbl + 2);
    A2.z = __shfl_sync(F, acc.z, gbl + 2); A2.w = __shfl_sync(F, acc.w, gbl + 2);
    A3.x = __shfl_sync(F, acc.x, gbl + 3); A3.y = __shfl_sync(F, acc.y, gbl + 3);
    A3.z = __shfl_sync(F, acc.z, gbl + 3); A3.w = __shfl_sync(F, acc.w, gbl + 3);

    if (valid && k >= 4) {
        const int i = k - 4;
        float4 R;
        R.x = acc.x * A0.x + acc.y * A1.x + acc.z * A2.x + acc.w * A3.x;
        R.y = acc.x * A0.y + acc.y * A1.y + acc.z * A2.y + acc.w * A3.y;
        R.z = acc.x * A0.z + acc.y * A1.z + acc.z * A2.z + acc.w * A3.z;
        R.w = acc.x * A0.w + acc.y * A1.w + acc.z * A2.w + acc.w * A3.w;
        ((float4*)out_w)[idx * 4 + i] = R;
        if (i < 3)
            out_xd[idx * 3 + i] = acc.x * sx + acc.y * sy + acc.z * sz + acc.w;
    }
}

// ---------------------------------------------------------------------------
// deform for MASKED points: pure coalesced streaming of g_pm records.
// ---------------------------------------------------------------------------
__global__ void __launch_bounds__(256) deform_masked_kernel(
    const float* __restrict__ xc, const float* __restrict__ shape_off,
    const float* __restrict__ pose_off, const float* __restrict__ poseoff_ori,
    float* __restrict__ out_xd, float* __restrict__ out_w, int N)
{
    const int cnt = g_cnt;
    const int slot = blockIdx.x * 32 + (threadIdx.x >> 3);
    if (blockIdx.x * 32 >= cnt) return;            // uniform per block
    const int k = threadIdx.x & 7;
    const bool valid = slot < cnt;
    const int nc = g_midx[valid ? slot : cnt - 1];
    const int b = blockIdx.y;
    const long idx = (long)b * N + nc;

    const float px = xc[idx * 3 + 0], py = xc[idx * 3 + 1], pz = xc[idx * 3 + 2];
    const int sel = (k < 4) ? k : (b + 1) * 4 + (k - 4);
    float4 acc = g_pm[(long)nc * 20 + sel];

    epilogue(acc, k, nc, idx, valid, px, py, pz,
             shape_off, pose_off, poseoff_ori, out_xd, out_w);
}

// ---------------------------------------------------------------------------
// deform for UNMASKED points: trilinear gather of pre-blended voxel matrices.
// ---------------------------------------------------------------------------
__global__ void __launch_bounds__(256) deform_unmasked_kernel(
    const float* __restrict__ xc, const float* __restrict__ shape_off,
    const float* __restrict__ pose_off, const float* __restrict__ poseoff_ori,
    const float* __restrict__ offk, const float* __restrict__ sclk,
    float* __restrict__ out_xd, float* __restrict__ out_w, int N)
{
    const int cnt = g_ucnt;
    const int slot = blockIdx.x * 32 + (threadIdx.x >> 3);
    if (blockIdx.x * 32 >= cnt) return;            // uniform per block
    const int k = threadIdx.x & 7;
    const bool valid = slot < cnt;
    const int nc = g_uidx[valid ? slot : cnt - 1];
    const int b = blockIdx.y;
    const long idx = (long)b * N + nc;

    const float px = xc[idx * 3 + 0], py = xc[idx * 3 + 1], pz = xc[idx * 3 + 2];
    const int sel = (k < 4) ? k : (b + 1) * 4 + (k - 4);

    const float fx = (px + offk[0]) * sclk[0];
    const float fy = (py + offk[1]) * sclk[1];
    const float fz = (pz + offk[2]) * sclk[2];
    float ix = fminf(fmaxf((fx + 1.0f) * 0.5f * (float)(WV - 1), 0.0f), (float)(WV - 1));
    float iy = fminf(fmaxf((fy + 1.0f) * 0.5f * (float)(HV - 1), 0.0f), (float)(HV - 1));
    float iz = fminf(fmaxf((fz + 1.0f) * 0.5f * (float)(DV - 1), 0.0f), (float)(DV - 1));
    float xf = floorf(ix), yf = floorf(iy), zf = floorf(iz);
    float wx = ix - xf, wy = iy - yf, wz = iz - zf;
    int x0 = (int)xf, y0 = (int)yf, z0 = (int)zf;
    int x1 = min(x0 + 1, WV - 1), y1 = min(y0 + 1, HV - 1), z1 = min(z0 + 1, DV - 1);
    int r00 = (z0 * HV + y0) * WV, r01 = (z0 * HV + y1) * WV;
    int r10 = (z1 * HV + y0) * WV, r11 = (z1 * HV + y1) * WV;
    float mx = 1.0f - wx, my = 1.0f - wy, mz = 1.0f - wz;

    int   vs[8];
    float cw[8];
    vs[0] = r00 + x0; cw[0] = mz * my * mx;
    vs[1] = r00 + x1; cw[1] = mz * my * wx;
    vs[2] = r01 + x0; cw[2] = mz * wy * mx;
    vs[3] = r01 + x1; cw[3] = mz * wy * wx;
    vs[4] = r10 + x0; cw[4] = wz * my * mx;
    vs[5] = r10 + x1; cw[5] = wz * my * wx;
    vs[6] = r11 + x0; cw[6] = wz * wy * mx;
    vs[7] = r11 + x1; cw[7] = wz * wy * wx;

    unsigned long long a0 = 0ull, a1 = 0ull;
    #pragma unroll
    for (int t = 0; t < 8; ++t) {
        ulonglong2 r = *(const ulonglong2*)&g_mv[(long)vs[t] * 20 + sel];
        unsigned long long s = splat2(cw[t]);
        a0 = ffma2(s, r.x, a0);
        a1 = ffma2(s, r.y, a1);
    }
    float4 acc = pack2(a0, a1);

    epilogue(acc, k, nc, idx, valid, px, py, pz,
             shape_off, pose_off, poseoff_ori, out_xd, out_w);
}

// ---------------------------------------------------------------------------
// Host: resolve inputs by exact element count (ordering-independent binding).
// ---------------------------------------------------------------------------
extern "C" void kernel_launch(void* const* d_in, const int* in_sizes, int n_in,
                              void* d_out, int out_size) {
    const float *tfs = nullptr, *tfs_inv = nullptr, *poseoff_ori = nullptr,
                *lbsw = nullptr, *vol = nullptr;
    const void  *mask = nullptr;
    const float *p3M[3] = {nullptr, nullptr, nullptr};
    const float *psm[2] = {nullptr, nullptr};
    int c3 = 0, cs = 0;
    int idx_mask = -1, idx_first3M = -1;

    for (int i = 0; i < n_in; i++) {
        switch (in_sizes[i]) {
            case 3520:     tfs = (const float*)d_in[i]; break;
            case 880:      tfs_inv = (const float*)d_in[i]; break;
            case 750000:   poseoff_ori = (const float*)d_in[i]; break;
            case 13750000: lbsw = (const float*)d_in[i]; break;
            case 250000:   mask = d_in[i]; idx_mask = i; break;
            case 3604480:  vol = (const float*)d_in[i]; break;
            case 3:        if (cs < 2) psm[cs++] = (const float*)d_in[i]; break;
            case 3000000:
                if (c3 == 0) idx_first3M = i;
                if (c3 < 3) p3M[c3++] = (const float*)d_in[i];
                break;
            default: break;
        }
    }

    const int N = 250000, B = 4;

    const float* xc        = (idx_mask >= 0 && idx_first3M >= 0 && idx_mask < idx_first3M)
                             ? p3M[2] : p3M[0];
    const float* shape_off = (xc == p3M[0]) ? p3M[1] : p3M[0];
    const float* pose_off  = (xc == p3M[0]) ? p3M[2] : p3M[1];
    const float* offk = psm[0];
    const float* sclk = psm[1];

    float* out_xd = (float*)d_out;
    float* out_w  = out_xd + (size_t)B * N * 3;

    reset_flag_kernel<<<1, 1>>>();
    detect_mask_kernel<<<(65536 + 255) / 256, 256>>>((const unsigned char*)mask, N);
    compact_mask_kernel<<<(N + 255) / 256, 256>>>(mask, N);

    dim3 g1(NVOX / 512, 5);
    preblend_vox_kernel<<<g1, 256>>>(vol, tfs, tfs_inv);

    dim3 b2(32, 5);
    preblend_pts_kernel<<<(N + 63) / 64, b2>>>(lbsw, tfs, tfs_inv);

    dim3 gm((N + 31) / 32, 4);
    deform_masked_kernel<<<gm, 256>>>(xc, shape_off, pose_off, poseoff_ori,
                                      out_xd, out_w, N);
    deform_unmasked_kernel<<<gm, 256>>>(xc, shape_off, pose_off, poseoff_ori,
                                        offk, sclk, out_xd, out_w, N);
}

// round 15
// speedup vs baseline: 1.0940x; 1.0940x over previous
#include <cuda_runtime.h>
#include <cstdint>

#define DV 16
#define HV 64
#define WV 64
#define NVOX (DV*HV*WV)   /* 65536 voxels */
#define NMAX 250000
#define JJ   55

// Scratch (no allocations allowed)
__device__ __align__(16) float4 g_mv[NVOX * 20];   // 20MB: per-voxel [A,C0..C3] rows
__device__ __align__(16) float4 g_pm[NMAX * 20];   // 80MB: per-point rows (masked only)
__device__ int g_midx[NMAX];                       // compacted masked indices (for P2)
__device__ int g_list[NMAX];                       // block-locally partitioned ids (sign bit = masked)
__device__ int g_cnt;                              // masked count
__device__ int g_mask_is_u8;

// ---------------------------------------------------------------------------
// helpers
// ---------------------------------------------------------------------------
static __device__ __forceinline__ unsigned long long ffma2(
    unsigned long long a, unsigned long long b, unsigned long long c) {
    unsigned long long d;
    asm("fma.rn.f32x2 %0, %1, %2, %3;" : "=l"(d) : "l"(a), "l"(b), "l"(c));
    return d;
}
static __device__ __forceinline__ unsigned long long splat2(float w) {
    unsigned long long d;
    asm("mov.b64 %0, {%1, %1};" : "=l"(d) : "f"(w));
    return d;
}
static __device__ __forceinline__ float4 pack2(unsigned long long a, unsigned long long b) {
    float4 r;
    asm("mov.b64 {%0, %1}, %2;" : "=f"(r.x), "=f"(r.y) : "l"(a));
    asm("mov.b64 {%0, %1}, %2;" : "=f"(r.z), "=f"(r.w) : "l"(b));
    return r;
}

// ---------------------------------------------------------------------------
// mask dtype detection + reset
// ---------------------------------------------------------------------------
__global__ void reset_flag_kernel() { g_mask_is_u8 = 0; g_cnt = 0; }

__global__ void detect_mask_kernel(const unsigned char* __restrict__ m, int N) {
    int i = blockIdx.x * 256 + threadIdx.x;
    int limit = N < 65536 ? N : 65536;
    if (i < limit && (i & 3) != 0 && m[i] != 0)
        atomicOr(&g_mask_is_u8, 1);
}

static __device__ __forceinline__ bool read_mask(const void* mask_raw, int n) {
    if (g_mask_is_u8) return ((const unsigned char*)mask_raw)[n] != 0;
    return ((const int*)mask_raw)[n] != 0;
}

// ---------------------------------------------------------------------------
// compact masked indices globally (order nondeterministic; used ONLY by
// preblend_pts whose outputs are keyed by the point index -> deterministic)
// ---------------------------------------------------------------------------
__global__ void compact_mask_kernel(const void* __restrict__ mask_raw, int N) {
    int i = blockIdx.x * 256 + threadIdx.x;
    if (i < N && read_mask(mask_raw, i))
        g_midx[atomicAdd(&g_cnt, 1)] = i;
}

// ---------------------------------------------------------------------------
// block-local partition: within each 256-point tile, list masked points first
// then unmasked (deterministic ballot ranks). Sign bit marks masked.
// Keeps warp homogeneity AND cache locality for the deform kernel.
// ---------------------------------------------------------------------------
__global__ void __launch_bounds__(256) fill_local_kernel(
    const void* __restrict__ mask_raw, int N)
{
    const int base = blockIdx.x * 256;
    const int i = base + threadIdx.x;
    bool m = (i < N) ? read_mask(mask_raw, i) : false;
    bool u = (i < N) && !m;
    unsigned bm = __ballot_sync(0xffffffffu, m);
    unsigned bu = __ballot_sync(0xffffffffu, u);
    __shared__ int wm[8], wu[8];
    const int w = threadIdx.x >> 5, l = threadIdx.x & 31;
    if (l == 0) { wm[w] = __popc(bm); wu[w] = __popc(bu); }
    __syncthreads();
    int bcnt = 0;
    #pragma unroll
    for (int x = 0; x < 8; ++x) bcnt += wm[x];
    int pm = 0, pu = 0;
    for (int x = 0; x < w; ++x) { pm += wm[x]; pu += wu[x]; }
    const unsigned lt = (1u << l) - 1u;
    if (m) g_list[base + pm + __popc(bm & lt)] = i | 0x80000000;
    if (u) g_list[base + bcnt + pu + __popc(bu & lt)] = i;
}

// ---------------------------------------------------------------------------
// P1: per-voxel pre-blend, TWO voxels per thread.
// blockIdx.y = m (0 = tfs_inv, 1..4 = tfs batch m-1).  M[v] = sum_j vol[j][v]*T_j
// ---------------------------------------------------------------------------
__global__ void __launch_bounds__(256) preblend_vox_kernel(
    const float* __restrict__ vol, const float* __restrict__ tfs,
    const float* __restrict__ tfs_inv)
{
    const int m = blockIdx.y;
    const int v = (blockIdx.x * 256 + threadIdx.x) * 2;
    __shared__ float4 s_T[JJ * 4];
    {
        const float* src = (m == 0) ? tfs_inv : tfs + (m - 1) * JJ * 16;
        float* st = (float*)s_T;
        for (int e = threadIdx.x; e < JJ * 16; e += 256) st[e] = src[e];
    }
    __syncthreads();

    unsigned long long A0=0,A1=0,A2=0,A3=0,A4=0,A5=0,A6=0,A7=0;
    unsigned long long B0=0,B1=0,B2=0,B3=0,B4=0,B5=0,B6=0,B7=0;
    #pragma unroll 11
    for (int j = 0; j < JJ; ++j) {
        float2 w2 = *(const float2*)&vol[j * NVOX + v];
        unsigned long long sa = splat2(w2.x);
        unsigned long long sb = splat2(w2.y);
        const ulonglong2* rp = (const ulonglong2*)&s_T[j * 4];
        ulonglong2 r0 = rp[0], r1 = rp[1], r2 = rp[2], r3 = rp[3];
        A0 = ffma2(sa, r0.x, A0); A1 = ffma2(sa, r0.y, A1);
        A2 = ffma2(sa, r1.x, A2); A3 = ffma2(sa, r1.y, A3);
        A4 = ffma2(sa, r2.x, A4); A5 = ffma2(sa, r2.y, A5);
        A6 = ffma2(sa, r3.x, A6); A7 = ffma2(sa, r3.y, A7);
        B0 = ffma2(sb, r0.x, B0); B1 = ffma2(sb, r0.y, B1);
        B2 = ffma2(sb, r1.x, B2); B3 = ffma2(sb, r1.y, B3);
        B4 = ffma2(sb, r2.x, B4); B5 = ffma2(sb, r2.y, B5);
        B6 = ffma2(sb, r3.x, B6); B7 = ffma2(sb, r3.y, B7);
    }
    float4* out = &g_mv[v * 20 + m * 4];
    out[0] = pack2(A0, A1); out[1] = pack2(A2, A3);
    out[2] = pack2(A4, A5); out[3] = pack2(A6, A7);
    out = &g_mv[(v + 1) * 20 + m * 4];
    out[0] = pack2(B0, B1); out[1] = pack2(B2, B3);
    out[2] = pack2(B4, B5); out[3] = pack2(B6, B7);
}

// ---------------------------------------------------------------------------
// P2: per-point pre-blend over the COMPACTED masked list.
// block = (32, 5): thread (p, m) handles compacted slots i0+p and i0+p+32.
// ---------------------------------------------------------------------------
__global__ void __launch_bounds__(160) preblend_pts_kernel(
    const float* __restrict__ lbsw, const float* __restrict__ tfs,
    const float* __restrict__ tfs_inv)
{
    const int cnt = g_cnt;
    const int i0 = blockIdx.x * 64;
    if (i0 >= cnt) return;

    __shared__ float4 s_T[5][JJ * 4];
    __shared__ float  s_w[JJ][66];
    __shared__ int    s_idx[64];
    const int tid = threadIdx.y * 32 + threadIdx.x;
    {
        float* st = (float*)s_T;
        for (int e = tid; e < 5 * JJ * 16; e += 160) {
            int m = e / (JJ * 16), q = e - m * (JJ * 16);
            st[e] = (m == 0) ? tfs_inv[q] : tfs[(m - 1) * JJ * 16 + q];
        }
        if (tid < 64) s_idx[tid] = (i0 + tid < cnt) ? g_midx[i0 + tid] : -1;
    }
    __syncthreads();
    {
        int cnt2 = min(64, cnt - i0);
        for (int e = tid; e < cnt2 * JJ; e += 160) {
            int p = e / JJ, j = e - p * JJ;
            s_w[j][p] = lbsw[(long)s_idx[p] * JJ + j];
        }
    }
    __syncthreads();

    const int p = threadIdx.x, m = threadIdx.y;
    const int nA = s_idx[p], nB = s_idx[p + 32];

    unsigned long long A0=0,A1=0,A2=0,A3=0,A4=0,A5=0,A6=0,A7=0;
    unsigned long long B0=0,B1=0,B2=0,B3=0,B4=0,B5=0,B6=0,B7=0;
    #pragma unroll 5
    for (int j = 0; j < JJ; ++j) {
        const ulonglong2* rp = (const ulonglong2*)&s_T[m][j * 4];
        ulonglong2 r0 = rp[0], r1 = rp[1], r2 = rp[2], r3 = rp[3];
        unsigned long long sa = splat2(s_w[j][p]);
        unsigned long long sb = splat2(s_w[j][p + 32]);
        A0 = ffma2(sa, r0.x, A0); A1 = ffma2(sa, r0.y, A1);
        A2 = ffma2(sa, r1.x, A2); A3 = ffma2(sa, r1.y, A3);
        A4 = ffma2(sa, r2.x, A4); A5 = ffma2(sa, r2.y, A5);
        A6 = ffma2(sa, r3.x, A6); A7 = ffma2(sa, r3.y, A7);
        B0 = ffma2(sb, r0.x, B0); B1 = ffma2(sb, r0.y, B1);
        B2 = ffma2(sb, r1.x, B2); B3 = ffma2(sb, r1.y, B3);
        B4 = ffma2(sb, r2.x, B4); B5 = ffma2(sb, r2.y, B5);
        B6 = ffma2(sb, r3.x, B6); B7 = ffma2(sb, r3.y, B7);
    }
    if (nA >= 0) {
        float4* out = &g_pm[(long)nA * 20 + m * 4];
        out[0] = pack2(A0, A1); out[1] = pack2(A2, A3);
        out[2] = pack2(A4, A5); out[3] = pack2(A6, A7);
    }
    if (nB >= 0) {
        float4* out = &g_pm[(long)nB * 20 + m * 4];
        out[0] = pack2(B0, B1); out[1] = pack2(B2, B3);
        out[2] = pack2(B4, B5); out[3] = pack2(B6, B7);
    }
}

// ---------------------------------------------------------------------------
// Main (per-batch grid.y, batch-specific xc):
// 8 lanes per point, points taken from g_list (block-locally partitioned so
// warps are mask-homogeneous). Lane k<4 builds A row k; lane k>=4 builds
// C_b row k-4 via packed-f32x2 trilinear interp (or direct g_pm load if
// masked). Epilogue reassembles across the 8-lane group.
// ---------------------------------------------------------------------------
__global__ void __launch_bounds__(256) deform_kernel(
    const float* __restrict__ xc, const float* __restrict__ shape_off,
    const float* __restrict__ pose_off, const float* __restrict__ poseoff_ori,
    const float* __restrict__ offk, const float* __restrict__ sclk,
    float* __restrict__ out_xd, float* __restrict__ out_w, int N)
{
    const int b = blockIdx.y;
    const int g = threadIdx.x >> 3;            // point slot in block (0..31)
    const int k = threadIdx.x & 7;             // row slot within group
    const int slot = blockIdx.x * 32 + g;
    const int sc = slot < N ? slot : N - 1;    // clamp; no early return (shuffles)
    const int raw = g_list[sc];
    const bool msk = raw < 0;
    const int nc = raw & 0x7fffffff;
    const bool valid = slot < N;
    const long idx = (long)b * N + nc;

    const float px = xc[idx * 3 + 0], py = xc[idx * 3 + 1], pz = xc[idx * 3 + 2];
    const int sel = (k < 4) ? k : (b + 1) * 4 + (k - 4);

    float4 acc;
    if (msk) {
        acc = g_pm[(long)nc * 20 + sel];
    } else {
        const float fx = (px + offk[0]) * sclk[0];
        const float fy = (py + offk[1]) * sclk[1];
        const float fz = (pz + offk[2]) * sclk[2];
        float ix = fminf(fmaxf((fx + 1.0f) * 0.5f * (float)(WV - 1), 0.0f), (float)(WV - 1));
        float iy = fminf(fmaxf((fy + 1.0f) * 0.5f * (float)(HV - 1), 0.0f), (float)(HV - 1));
        float iz = fminf(fmaxf((fz + 1.0f) * 0.5f * (float)(DV - 1), 0.0f), (float)(DV - 1));
        float xf = floorf(ix), yf = floorf(iy), zf = floorf(iz);
        float wx = ix - xf, wy = iy - yf, wz = iz - zf;
        int x0 = (int)xf, y0 = (int)yf, z0 = (int)zf;
        int x1 = min(x0 + 1, WV - 1), y1 = min(y0 + 1, HV - 1), z1 = min(z0 + 1, DV - 1);
        int r00 = (z0 * HV + y0) * WV, r01 = (z0 * HV + y1) * WV;
        int r10 = (z1 * HV + y0) * WV, r11 = (z1 * HV + y1) * WV;
        float mx = 1.0f - wx, my = 1.0f - wy, mz = 1.0f - wz;

        int   vs[8];
        float cw[8];
        vs[0] = r00 + x0; cw[0] = mz * my * mx;
        vs[1] = r00 + x1; cw[1] = mz * my * wx;
        vs[2] = r01 + x0; cw[2] = mz * wy * mx;
        vs[3] = r01 + x1; cw[3] = mz * wy * wx;
        vs[4] = r10 + x0; cw[4] = wz * my * mx;
        vs[5] = r10 + x1; cw[5] = wz * my * wx;
        vs[6] = r11 + x0; cw[6] = wz * wy * mx;
        vs[7] = r11 + x1; cw[7] = wz * wy * wx;

        unsigned long long a0 = 0ull, a1 = 0ull;
        #pragma unroll
        for (int t = 0; t < 8; ++t) {
            ulonglong2 r = *(const ulonglong2*)&g_mv[(long)vs[t] * 20 + sel];
            unsigned long long s = splat2(cw[t]);
            a0 = ffma2(s, r.x, a0);
            a1 = ffma2(s, r.y, a1);
        }
        acc = pack2(a0, a1);
    }

    // ----- epilogue -----
    const unsigned F = 0xffffffffu;
    const int lane = threadIdx.x & 31;
    const int gbl  = lane & ~7;                // group base lane within warp

    float aval = acc.x * px + acc.y * py + acc.z * pz + acc.w;
    if (k < 3)
        aval += -poseoff_ori[(long)nc * 3 + k]
              + shape_off[idx * 3 + k] + pose_off[idx * 3 + k];

    float sx = __shfl_sync(F, aval, gbl + 0);
    float sy = __shfl_sync(F, aval, gbl + 1);
    float sz = __shfl_sync(F, aval, gbl + 2);

    float4 A0, A1, A2, A3;
    A0.x = __shfl_sync(F, acc.x, gbl + 0); A0.y = __shfl_sync(F, acc.y, gbl + 0);
    A0.z = __shfl_sync(F, acc.z, gbl + 0); A0.w = __shfl_sync(F, acc.w, gbl + 0);
    A1.x = __shfl_sync(F, acc.x, gbl + 1); A1.y = __shfl_sync(F, acc.y, gbl + 1);
    A1.z = __shfl_sync(F, acc.z, gbl + 1); A1.w = __shfl_sync(F, acc.w, gbl + 1);
    A2.x = __shfl_sync(F, acc.x, gbl + 2); A2.y = __shfl_sync(F, acc.y, gbl + 2);
    A2.z = __shfl_sync(F, acc.z, gbl + 2); A2.w = __shfl_sync(F, acc.w, gbl + 2);
    A3.x = __shfl_sync(F, acc.x, gbl + 3); A3.y = __shfl_sync(F, acc.y, gbl + 3);
    A3.z = __shfl_sync(F, acc.z, gbl + 3); A3.w = __shfl_sync(F, acc.w, gbl + 3);

    if (valid && k >= 4) {
        const int i = k - 4;                   // C row index
        float4 R;                              // R row i = C_i @ A
        R.x = acc.x * A0.x + acc.y * A1.x + acc.z * A2.x + acc.w * A3.x;
        R.y = acc.x * A0.y + acc.y * A1.y + acc.z * A2.y + acc.w * A3.y;
        R.z = acc.x * A0.z + acc.y * A1.z + acc.z * A2.z + acc.w * A3.z;
        R.w = acc.x * A0.w + acc.y * A1.w + acc.z * A2.w + acc.w * A3.w;
        ((float4*)out_w)[idx * 4 + i] = R;
        if (i < 3)
            out_xd[idx * 3 + i] = acc.x * sx + acc.y * sy + acc.z * sz + acc.w;
    }
}

// ---------------------------------------------------------------------------
// Host: resolve inputs by exact element count (ordering-independent binding).
// ---------------------------------------------------------------------------
extern "C" void kernel_launch(void* const* d_in, const int* in_sizes, int n_in,
                              void* d_out, int out_size) {
    const float *tfs = nullptr, *tfs_inv = nullptr, *poseoff_ori = nullptr,
                *lbsw = nullptr, *vol = nullptr;
    const void  *mask = nullptr;
    const float *p3M[3] = {nullptr, nullptr, nullptr};
    const float *psm[2] = {nullptr, nullptr};
    int c3 = 0, cs = 0;
    int idx_mask = -1, idx_first3M = -1;

    for (int i = 0; i < n_in; i++) {
        switch (in_sizes[i]) {
            case 3520:     tfs = (const float*)d_in[i]; break;
            case 880:      tfs_inv = (const float*)d_in[i]; break;
            case 750000:   poseoff_ori = (const float*)d_in[i]; break;
            case 13750000: lbsw = (const float*)d_in[i]; break;
            case 250000:   mask = d_in[i]; idx_mask = i; break;
            case 3604480:  vol = (const float*)d_in[i]; break;
            case 3:        if (cs < 2) psm[cs++] = (const float*)d_in[i]; break;
            case 3000000:
                if (c3 == 0) idx_first3M = i;
                if (c3 < 3) p3M[c3++] = (const float*)d_in[i];
                break;
            default: break;
        }
    }

    const int N = 250000, B = 4;

    const float* xc        = (idx_mask >= 0 && idx_first3M >= 0 && idx_mask < idx_first3M)
                             ? p3M[2] : p3M[0];
    const float* shape_off = (xc == p3M[0]) ? p3M[1] : p3M[0];
    const float* pose_off  = (xc == p3M[0]) ? p3M[2] : p3M[1];
    const float* offk = psm[0];
    const float* sclk = psm[1];

    float* out_xd = (float*)d_out;
    float* out_w  = out_xd + (size_t)B * N * 3;

    reset_flag_kernel<<<1, 1>>>();
    detect_mask_kernel<<<(65536 + 255) / 256, 256>>>((const unsigned char*)mask, N);
    compact_mask_kernel<<<(N + 255) / 256, 256>>>(mask, N);
    fill_local_kernel<<<(N + 255) / 256, 256>>>(mask, N);

    dim3 g1(NVOX / 512, 5);
    preblend_vox_kernel<<<g1, 256>>>(vol, tfs, tfs_inv);

    dim3 b2(32, 5);
    preblend_pts_kernel<<<(N + 63) / 64, b2>>>(lbsw, tfs, tfs_inv);

    dim3 g3((N + 31) / 32, 4);
    deform_kernel<<<g3, 256>>>(xc, shape_off, pose_off, poseoff_ori,
                               offk, sclk, out_xd, out_w, N);
}

// round 16
// speedup vs baseline: 1.2758x; 1.1662x over previous
#include <cuda_runtime.h>
#include <cstdint>

#define DV 16
#define HV 64
#define WV 64
#define NVOX (DV*HV*WV)   /* 65536 voxels */
#define NMAX 250000
#define JJ   55

// Scratch (no allocations allowed)
__device__ __align__(16) float4 g_mv[NVOX * 20];   // 20MB: per-voxel [A,C0..C3] rows
__device__ __align__(16) float4 g_pm[NMAX * 20];   // 80MB: per-point rows (masked only)
__device__ int g_midx[NMAX];                       // compacted masked indices (for P2)
__device__ int g_list[NMAX];                       // block-locally partitioned ids (sign bit = masked)
__device__ int g_cnt;                              // masked count
__device__ int g_mask_is_u8;

// ---------------------------------------------------------------------------
// helpers
// ---------------------------------------------------------------------------
static __device__ __forceinline__ unsigned long long ffma2(
    unsigned long long a, unsigned long long b, unsigned long long c) {
    unsigned long long d;
    asm("fma.rn.f32x2 %0, %1, %2, %3;" : "=l"(d) : "l"(a), "l"(b), "l"(c));
    return d;
}
static __device__ __forceinline__ unsigned long long splat2(float w) {
    unsigned long long d;
    asm("mov.b64 %0, {%1, %1};" : "=l"(d) : "f"(w));
    return d;
}
static __device__ __forceinline__ float4 pack2(unsigned long long a, unsigned long long b) {
    float4 r;
    asm("mov.b64 {%0, %1}, %2;" : "=f"(r.x), "=f"(r.y) : "l"(a));
    asm("mov.b64 {%0, %1}, %2;" : "=f"(r.z), "=f"(r.w) : "l"(b));
    return r;
}

// ---------------------------------------------------------------------------
// mask dtype detection + reset
// ---------------------------------------------------------------------------
__global__ void reset_flag_kernel() { g_mask_is_u8 = 0; g_cnt = 0; }

__global__ void detect_mask_kernel(const unsigned char* __restrict__ m, int N) {
    int i = blockIdx.x * 256 + threadIdx.x;
    int limit = N < 65536 ? N : 65536;
    if (i < limit && (i & 3) != 0 && m[i] != 0)
        atomicOr(&g_mask_is_u8, 1);
}

static __device__ __forceinline__ bool read_mask(const void* mask_raw, int n) {
    if (g_mask_is_u8) return ((const unsigned char*)mask_raw)[n] != 0;
    return ((const int*)mask_raw)[n] != 0;
}

// ---------------------------------------------------------------------------
// fused partition kernel:
//  - g_list: per-256-tile [masked | unmasked] order (deterministic ranks,
//    sign bit marks masked) -> warp-homogeneous AND cache-local deform.
//  - g_midx: global masked compaction via one block-aggregated atomic
//    (order nondeterministic; only consumed by preblend_pts whose outputs
//    are keyed by point index -> deterministic results).
// ---------------------------------------------------------------------------
__global__ void __launch_bounds__(256) fill_local_kernel(
    const void* __restrict__ mask_raw, int N)
{
    const int base = blockIdx.x * 256;
    const int i = base + threadIdx.x;
    bool m = (i < N) ? read_mask(mask_raw, i) : false;
    bool u = (i < N) && !m;
    unsigned bm = __ballot_sync(0xffffffffu, m);
    unsigned bu = __ballot_sync(0xffffffffu, u);
    __shared__ int wm[8], wu[8];
    __shared__ int s_base;
    const int w = threadIdx.x >> 5, l = threadIdx.x & 31;
    if (l == 0) { wm[w] = __popc(bm); wu[w] = __popc(bu); }
    __syncthreads();
    int bcnt = 0;
    #pragma unroll
    for (int x = 0; x < 8; ++x) bcnt += wm[x];
    if (threadIdx.x == 0) s_base = atomicAdd(&g_cnt, bcnt);
    int pm = 0, pu = 0;
    for (int x = 0; x < w; ++x) { pm += wm[x]; pu += wu[x]; }
    __syncthreads();
    const unsigned lt = (1u << l) - 1u;
    if (m) {
        int r = pm + __popc(bm & lt);
        g_list[base + r] = i | 0x80000000;
        g_midx[s_base + r] = i;
    }
    if (u) g_list[base + bcnt + pu + __popc(bu & lt)] = i;
}

// ---------------------------------------------------------------------------
// P1: per-voxel pre-blend, TWO voxels per thread.
// blockIdx.y = m (0 = tfs_inv, 1..4 = tfs batch m-1).  M[v] = sum_j vol[j][v]*T_j
// ---------------------------------------------------------------------------
__global__ void __launch_bounds__(256) preblend_vox_kernel(
    const float* __restrict__ vol, const float* __restrict__ tfs,
    const float* __restrict__ tfs_inv)
{
    const int m = blockIdx.y;
    const int v = (blockIdx.x * 256 + threadIdx.x) * 2;
    __shared__ float4 s_T[JJ * 4];
    {
        const float* src = (m == 0) ? tfs_inv : tfs + (m - 1) * JJ * 16;
        float* st = (float*)s_T;
        for (int e = threadIdx.x; e < JJ * 16; e += 256) st[e] = src[e];
    }
    __syncthreads();

    unsigned long long A0=0,A1=0,A2=0,A3=0,A4=0,A5=0,A6=0,A7=0;
    unsigned long long B0=0,B1=0,B2=0,B3=0,B4=0,B5=0,B6=0,B7=0;
    #pragma unroll 11
    for (int j = 0; j < JJ; ++j) {
        float2 w2 = *(const float2*)&vol[j * NVOX + v];
        unsigned long long sa = splat2(w2.x);
        unsigned long long sb = splat2(w2.y);
        const ulonglong2* rp = (const ulonglong2*)&s_T[j * 4];
        ulonglong2 r0 = rp[0], r1 = rp[1], r2 = rp[2], r3 = rp[3];
        A0 = ffma2(sa, r0.x, A0); A1 = ffma2(sa, r0.y, A1);
        A2 = ffma2(sa, r1.x, A2); A3 = ffma2(sa, r1.y, A3);
        A4 = ffma2(sa, r2.x, A4); A5 = ffma2(sa, r2.y, A5);
        A6 = ffma2(sa, r3.x, A6); A7 = ffma2(sa, r3.y, A7);
        B0 = ffma2(sb, r0.x, B0); B1 = ffma2(sb, r0.y, B1);
        B2 = ffma2(sb, r1.x, B2); B3 = ffma2(sb, r1.y, B3);
        B4 = ffma2(sb, r2.x, B4); B5 = ffma2(sb, r2.y, B5);
        B6 = ffma2(sb, r3.x, B6); B7 = ffma2(sb, r3.y, B7);
    }
    float4* out = &g_mv[v * 20 + m * 4];
    out[0] = pack2(A0, A1); out[1] = pack2(A2, A3);
    out[2] = pack2(A4, A5); out[3] = pack2(A6, A7);
    out = &g_mv[(v + 1) * 20 + m * 4];
    out[0] = pack2(B0, B1); out[1] = pack2(B2, B3);
    out[2] = pack2(B4, B5); out[3] = pack2(B6, B7);
}

// ---------------------------------------------------------------------------
// P2: per-point pre-blend over the COMPACTED masked list.
// block = (32, 5): thread (p, m) handles compacted slots i0+p and i0+p+32.
// ---------------------------------------------------------------------------
__global__ void __launch_bounds__(160) preblend_pts_kernel(
    const float* __restrict__ lbsw, const float* __restrict__ tfs,
    const float* __restrict__ tfs_inv)
{
    const int cnt = g_cnt;
    const int i0 = blockIdx.x * 64;
    if (i0 >= cnt) return;

    __shared__ float4 s_T[5][JJ * 4];
    __shared__ float  s_w[JJ][66];
    __shared__ int    s_idx[64];
    const int tid = threadIdx.y * 32 + threadIdx.x;
    {
        float* st = (float*)s_T;
        for (int e = tid; e < 5 * JJ * 16; e += 160) {
            int m = e / (JJ * 16), q = e - m * (JJ * 16);
            st[e] = (m == 0) ? tfs_inv[q] : tfs[(m - 1) * JJ * 16 + q];
        }
        if (tid < 64) s_idx[tid] = (i0 + tid < cnt) ? g_midx[i0 + tid] : -1;
    }
    __syncthreads();
    {
        int cnt2 = min(64, cnt - i0);
        for (int e = tid; e < cnt2 * JJ; e += 160) {
            int p = e / JJ, j = e - p * JJ;
            s_w[j][p] = lbsw[(long)s_idx[p] * JJ + j];
        }
    }
    __syncthreads();

    const int p = threadIdx.x, m = threadIdx.y;
    const int nA = s_idx[p], nB = s_idx[p + 32];

    unsigned long long A0=0,A1=0,A2=0,A3=0,A4=0,A5=0,A6=0,A7=0;
    unsigned long long B0=0,B1=0,B2=0,B3=0,B4=0,B5=0,B6=0,B7=0;
    #pragma unroll 5
    for (int j = 0; j < JJ; ++j) {
        const ulonglong2* rp = (const ulonglong2*)&s_T[m][j * 4];
        ulonglong2 r0 = rp[0], r1 = rp[1], r2 = rp[2], r3 = rp[3];
        unsigned long long sa = splat2(s_w[j][p]);
        unsigned long long sb = splat2(s_w[j][p + 32]);
        A0 = ffma2(sa, r0.x, A0); A1 = ffma2(sa, r0.y, A1);
        A2 = ffma2(sa, r1.x, A2); A3 = ffma2(sa, r1.y, A3);
        A4 = ffma2(sa, r2.x, A4); A5 = ffma2(sa, r2.y, A5);
        A6 = ffma2(sa, r3.x, A6); A7 = ffma2(sa, r3.y, A7);
        B0 = ffma2(sb, r0.x, B0); B1 = ffma2(sb, r0.y, B1);
        B2 = ffma2(sb, r1.x, B2); B3 = ffma2(sb, r1.y, B3);
        B4 = ffma2(sb, r2.x, B4); B5 = ffma2(sb, r2.y, B5);
        B6 = ffma2(sb, r3.x, B6); B7 = ffma2(sb, r3.y, B7);
    }
    if (nA >= 0) {
        float4* out = &g_pm[(long)nA * 20 + m * 4];
        out[0] = pack2(A0, A1); out[1] = pack2(A2, A3);
        out[2] = pack2(A4, A5); out[3] = pack2(A6, A7);
    }
    if (nB >= 0) {
        float4* out = &g_pm[(long)nB * 20 + m * 4];
        out[0] = pack2(B0, B1); out[1] = pack2(B2, B3);
        out[2] = pack2(B4, B5); out[3] = pack2(B6, B7);
    }
}

// ---------------------------------------------------------------------------
// Main (per-batch grid.y, batch-specific xc):
// FOUR lanes per point (8 points/warp). Lane k owns A row k AND C_b row k.
// Per corner: lanes 0-3 load A rows 0-3 (64B run) + C rows 4b+4..7 (64B run)
// — identical coalescing to the 8-lane version, half the per-point overhead.
// Epilogue shuffles within the 4-lane quad.
// ---------------------------------------------------------------------------
__global__ void __launch_bounds__(256) deform_kernel(
    const float* __restrict__ xc, const float* __restrict__ shape_off,
    const float* __restrict__ pose_off, const float* __restrict__ poseoff_ori,
    const float* __restrict__ offk, const float* __restrict__ sclk,
    float* __restrict__ out_xd, float* __restrict__ out_w, int N)
{
    const int b = blockIdx.y;
    const int g = threadIdx.x >> 2;            // point slot in block (0..63)
    const int k = threadIdx.x & 3;             // matrix row owned by this lane
    const int slot = blockIdx.x * 64 + g;
    const int sc = slot < N ? slot : N - 1;    // clamp; no early return (shuffles)
    const int raw = g_list[sc];
    const bool msk = raw < 0;
    const int nc = raw & 0x7fffffff;
    const bool valid = slot < N;
    const long idx = (long)b * N + nc;

    const float px = xc[idx * 3 + 0], py = xc[idx * 3 + 1], pz = xc[idx * 3 + 2];
    const int selC = (b + 1) * 4 + k;

    float4 accA, accC;
    if (msk) {
        const float4* base = &g_pm[(long)nc * 20];
        accA = base[k];
        accC = base[selC];
    } else {
        const float fx = (px + offk[0]) * sclk[0];
        const float fy = (py + offk[1]) * sclk[1];
        const float fz = (pz + offk[2]) * sclk[2];
        float ix = fminf(fmaxf((fx + 1.0f) * 0.5f * (float)(WV - 1), 0.0f), (float)(WV - 1));
        float iy = fminf(fmaxf((fy + 1.0f) * 0.5f * (float)(HV - 1), 0.0f), (float)(HV - 1));
        float iz = fminf(fmaxf((fz + 1.0f) * 0.5f * (float)(DV - 1), 0.0f), (float)(DV - 1));
        float xf = floorf(ix), yf = floorf(iy), zf = floorf(iz);
        float wx = ix - xf, wy = iy - yf, wz = iz - zf;
        int x0 = (int)xf, y0 = (int)yf, z0 = (int)zf;
        int x1 = min(x0 + 1, WV - 1), y1 = min(y0 + 1, HV - 1), z1 = min(z0 + 1, DV - 1);
        int r00 = (z0 * HV + y0) * WV, r01 = (z0 * HV + y1) * WV;
        int r10 = (z1 * HV + y0) * WV, r11 = (z1 * HV + y1) * WV;
        float mx = 1.0f - wx, my = 1.0f - wy, mz = 1.0f - wz;

        int   vs[8];
        float cw[8];
        vs[0] = r00 + x0; cw[0] = mz * my * mx;
        vs[1] = r00 + x1; cw[1] = mz * my * wx;
        vs[2] = r01 + x0; cw[2] = mz * wy * mx;
        vs[3] = r01 + x1; cw[3] = mz * wy * wx;
        vs[4] = r10 + x0; cw[4] = wz * my * mx;
        vs[5] = r10 + x1; cw[5] = wz * my * wx;
        vs[6] = r11 + x0; cw[6] = wz * wy * mx;
        vs[7] = r11 + x1; cw[7] = wz * wy * wx;

        unsigned long long a0 = 0ull, a1 = 0ull, c0 = 0ull, c1 = 0ull;
        #pragma unroll
        for (int t = 0; t < 8; ++t) {
            const float4* base = &g_mv[(long)vs[t] * 20];
            ulonglong2 rA = *(const ulonglong2*)&base[k];
            ulonglong2 rC = *(const ulonglong2*)&base[selC];
            unsigned long long s = splat2(cw[t]);
            a0 = ffma2(s, rA.x, a0); a1 = ffma2(s, rA.y, a1);
            c0 = ffma2(s, rC.x, c0); c1 = ffma2(s, rC.y, c1);
        }
        accA = pack2(a0, a1);
        accC = pack2(c0, c1);
    }

    // ----- epilogue (quad-level) -----
    const unsigned F = 0xffffffffu;
    const int lane = threadIdx.x & 31;
    const int qb  = lane & ~3;                 // quad base lane

    float aval = accA.x * px + accA.y * py + accA.z * pz + accA.w;
    if (k < 3)
        aval += -poseoff_ori[(long)nc * 3 + k]
              + shape_off[idx * 3 + k] + pose_off[idx * 3 + k];

    float sx = __shfl_sync(F, aval, qb + 0);
    float sy = __shfl_sync(F, aval, qb + 1);
    float sz = __shfl_sync(F, aval, qb + 2);

    float4 A0, A1, A2, A3;
    A0.x = __shfl_sync(F, accA.x, qb + 0); A0.y = __shfl_sync(F, accA.y, qb + 0);
    A0.z = __shfl_sync(F, accA.z, qb + 0); A0.w = __shfl_sync(F, accA.w, qb + 0);
    A1.x = __shfl_sync(F, accA.x, qb + 1); A1.y = __shfl_sync(F, accA.y, qb + 1);
    A1.z = __shfl_sync(F, accA.z, qb + 1); A1.w = __shfl_sync(F, accA.w, qb + 1);
    A2.x = __shfl_sync(F, accA.x, qb + 2); A2.y = __shfl_sync(F, accA.y, qb + 2);
    A2.z = __shfl_sync(F, accA.z, qb + 2); A2.w = __shfl_sync(F, accA.w, qb + 2);
    A3.x = __shfl_sync(F, accA.x, qb + 3); A3.y = __shfl_sync(F, accA.y, qb + 3);
    A3.z = __shfl_sync(F, accA.z, qb + 3); A3.w = __shfl_sync(F, accA.w, qb + 3);

    if (valid) {
        float4 R;                              // R row k = C_k @ A
        R.x = accC.x * A0.x + accC.y * A1.x + accC.z * A2.x + accC.w * A3.x;
        R.y = accC.x * A0.y + accC.y * A1.y + accC.z * A2.y + accC.w * A3.y;
        R.z = accC.x * A0.z + accC.y * A1.z + accC.z * A2.z + accC.w * A3.z;
        R.w = accC.x * A0.w + accC.y * A1.w + accC.z * A2.w + accC.w * A3.w;
        ((float4*)out_w)[idx * 4 + k] = R;
        if (k < 3)
            out_xd[idx * 3 + k] = accC.x * sx + accC.y * sy + accC.z * sz + accC.w;
    }
}

// ---------------------------------------------------------------------------
// Host: resolve inputs by exact element count (ordering-independent binding).
// ---------------------------------------------------------------------------
extern "C" void kernel_launch(void* const* d_in, const int* in_sizes, int n_in,
                              void* d_out, int out_size) {
    const float *tfs = nullptr, *tfs_inv = nullptr, *poseoff_ori = nullptr,
                *lbsw = nullptr, *vol = nullptr;
    const void  *mask = nullptr;
    const float *p3M[3] = {nullptr, nullptr, nullptr};
    const float *psm[2] = {nullptr, nullptr};
    int c3 = 0, cs = 0;
    int idx_mask = -1, idx_first3M = -1;

    for (int i = 0; i < n_in; i++) {
        switch (in_sizes[i]) {
            case 3520:     tfs = (const float*)d_in[i]; break;
            case 880:      tfs_inv = (const float*)d_in[i]; break;
            case 750000:   poseoff_ori = (const float*)d_in[i]; break;
            case 13750000: lbsw = (const float*)d_in[i]; break;
            case 250000:   mask = d_in[i]; idx_mask = i; break;
            case 3604480:  vol = (const float*)d_in[i]; break;
            case 3:        if (cs < 2) psm[cs++] = (const float*)d_in[i]; break;
            case 3000000:
                if (c3 == 0) idx_first3M = i;
                if (c3 < 3) p3M[c3++] = (const float*)d_in[i];
                break;
            default: break;
        }
    }

    const int N = 250000, B = 4;

    const float* xc        = (idx_mask >= 0 && idx_first3M >= 0 && idx_mask < idx_first3M)
                             ? p3M[2] : p3M[0];
    const float* shape_off = (xc == p3M[0]) ? p3M[1] : p3M[0];
    const float* pose_off  = (xc == p3M[0]) ? p3M[2] : p3M[1];
    const float* offk = psm[0];
    const float* sclk = psm[1];

    float* out_xd = (float*)d_out;
    float* out_w  = out_xd + (size_t)B * N * 3;

    reset_flag_kernel<<<1, 1>>>();
    detect_mask_kernel<<<(65536 + 255) / 256, 256>>>((const unsigned char*)mask, N);
    fill_local_kernel<<<(N + 255) / 256, 256>>>(mask, N);

    dim3 g1(NVOX / 512, 5);
    preblend_vox_kernel<<<g1, 256>>>(vol, tfs, tfs_inv);

    dim3 b2(32, 5);
    preblend_pts_kernel<<<(N + 63) / 64, b2>>>(lbsw, tfs, tfs_inv);

    dim3 g3((N + 63) / 64, 4);
    deform_kernel<<<g3, 256>>>(xc, shape_off, pose_off, poseoff_ori,
                               offk, sclk, out_xd, out_w, N);
}